// round 2
// baseline (speedup 1.0000x reference)
#include <cuda_runtime.h>
#include <stdint.h>

// Multiplexer: out[b, :] = full_input[b, idx[b]*64 : (idx[b]+1)*64]
// BATCH = 262144, OUTPUT_DIM = 64, NB_CTRL_SIG = 16 (row width 1024 f32)

#define OUTPUT_DIM 64
#define ROW_WIDTH  1024          // OUTPUT_DIM * NB_CTRL_SIG
#define VECS_PER_ROW 16          // 64 floats / 4 per float4
#define THREADS 256
#define ROWS_PER_BLOCK (THREADS / VECS_PER_ROW)   // 16

__global__ void __launch_bounds__(THREADS, 8)
mux_gather_kernel(const float4* __restrict__ in,      // [BATCH, 256] float4 view
                  const int*    __restrict__ indices, // [BATCH]
                  float4*       __restrict__ out,     // [BATCH, 16] float4 view
                  int batch)
{
    int tid  = threadIdx.x;
    int row  = blockIdx.x * ROWS_PER_BLOCK + (tid >> 4);   // tid / 16
    int sub  = tid & 15;                                    // float4 slot within row
    if (row >= batch) return;

    int idx = __ldg(&indices[row]);                         // broadcast within 16 threads (L1)
    // float4 addressing: row stride = 1024/4 = 256 vec4s; block offset = idx*64/4 = idx*16
    const float4* src = in + (size_t)row * (ROW_WIDTH / 4) + idx * (OUTPUT_DIM / 4) + sub;
    float4*       dst = out + (size_t)row * (OUTPUT_DIM / 4) + sub;
    *dst = __ldg(src);
}

extern "C" void kernel_launch(void* const* d_in, const int* in_sizes, int n_in,
                              void* d_out, int out_size)
{
    const float* full_input = (const float*)d_in[0];
    const int*   indices    = (const int*)d_in[1];
    float*       out        = (float*)d_out;

    int batch = in_sizes[0] / ROW_WIDTH;   // 262144

    int blocks = (batch + ROWS_PER_BLOCK - 1) / ROWS_PER_BLOCK;
    mux_gather_kernel<<<blocks, THREADS>>>(
        (const float4*)full_input, indices, (float4*)out, batch);
}

// round 3
// speedup vs baseline: 1.4827x; 1.4827x over previous
#include <cuda_runtime.h>
#include <stdint.h>

// Multiplexer: out[b, :] = full_input[b, idx[b]*64 : (idx[b]+1)*64]
// BATCH = 262144, OUTPUT_DIM = 64, NB_CTRL_SIG = 16 (row width 1024 f32)

#define OUTPUT_DIM 64
#define ROW_WIDTH  1024          // OUTPUT_DIM * NB_CTRL_SIG
#define ROW_VECS   (ROW_WIDTH / 4)    // 256 float4 per input row
#define OUT_VECS   (OUTPUT_DIM / 4)   // 16 float4 per output row
#define THREADS    256
#define ROWS_PER_THREAD 4
#define ROWS_PER_BLOCK  (THREADS / 16 * ROWS_PER_THREAD)  // 64

__global__ void __launch_bounds__(THREADS, 8)
mux_gather4_kernel(const float4* __restrict__ in,      // [BATCH, 256] float4 view
                   const int4*   __restrict__ indices, // [BATCH/4] int4 view
                   float4*       __restrict__ out,     // [BATCH, 16] float4 view
                   int batch)
{
    int tid  = threadIdx.x;
    int g    = tid >> 4;          // group 0..15, each handles 4 consecutive rows
    int sub  = tid & 15;          // float4 slot within a row

    int row0 = blockIdx.x * ROWS_PER_BLOCK + g * ROWS_PER_THREAD;
    if (row0 >= batch) return;

    // One vectorized load grabs all 4 indices (row0 is 4-aligned).
    int4 iv = __ldg(&indices[row0 >> 2]);
    int idx[4] = {iv.x, iv.y, iv.z, iv.w};

    // 4 independent gather loads — issued back-to-back for MLP=4.
    float4 v[4];
#pragma unroll
    for (int i = 0; i < 4; i++) {
        const float4* src = in + (size_t)(row0 + i) * ROW_VECS
                               + idx[i] * OUT_VECS + sub;
        v[i] = __ldcs(src);
    }

#pragma unroll
    for (int i = 0; i < 4; i++) {
        __stcs(out + (size_t)(row0 + i) * OUT_VECS + sub, v[i]);
    }
}

extern "C" void kernel_launch(void* const* d_in, const int* in_sizes, int n_in,
                              void* d_out, int out_size)
{
    const float* full_input = (const float*)d_in[0];
    const int*   indices    = (const int*)d_in[1];
    float*       out        = (float*)d_out;

    int batch = in_sizes[0] / ROW_WIDTH;   // 262144

    int blocks = (batch + ROWS_PER_BLOCK - 1) / ROWS_PER_BLOCK;  // 4096
    mux_gather4_kernel<<<blocks, THREADS>>>(
        (const float4*)full_input, (const int4*)indices, (float4*)out, batch);
}